// round 8
// baseline (speedup 1.0000x reference)
#include <cuda_runtime.h>
#include <math.h>

// ---------------------------------------------------------------------------
// AttentionalLaneLSTM: M=4096, N=256, EMB=64, H=128, ENC=128, T=100.
// ---------------------------------------------------------------------------
#define M_MAX   4096
#define T_STEPS 100
#define EMBD    64
#define HID     128
#define GDIM    512
#define NOBS    256
#define ROWS    8       // batch rows per recurrent CTA
#define XROWS   16      // batch rows per xgate CTA

// Scratch (device globals — no dynamic allocation allowed)
__device__ float g_scores[NOBS * T_STEPS];                  // softmax attn
__device__ __align__(16) float g_Whp[2 * HID  * GDIM];      // [dir][k][u*4+g]
__device__ __align__(16) float g_Wip[2 * EMBD * GDIM];      // [dir][k][u*4+g]
// x-gates: [(dir*T+t)*M + m][u][4 gates]  (i,f,g,o) fp32
__device__ __align__(16) float g_xg[2L * T_STEPS * M_MAX * GDIM];
__device__ float g_pre[M_MAX * 1024];                       // concat features

// ---------------------------------------------------------------------------
// f32x2 helpers (FFMA2 via PTX fma.rn.f32x2 on sm_103a)
// ---------------------------------------------------------------------------
__device__ __forceinline__ unsigned long long pack2(float a, float b) {
    unsigned long long r;
    asm("mov.b64 %0, {%1,%2};" : "=l"(r) : "f"(a), "f"(b));
    return r;
}
__device__ __forceinline__ float2 unpack2(unsigned long long v) {
    float2 r;
    asm("mov.b64 {%0,%1}, %2;" : "=f"(r.x), "=f"(r.y) : "l"(v));
    return r;
}
__device__ __forceinline__ void fma2(unsigned long long& acc,
                                     unsigned long long a, unsigned long long b) {
    asm("fma.rn.f32x2 %0, %1, %2, %0;" : "+l"(acc) : "l"(a), "l"(b));
}

__device__ __forceinline__ float sigf(float x) {
    return __fdividef(1.0f, 1.0f + __expf(-x));
}
__device__ __forceinline__ float tanhfast(float x) {
    return __fdividef(2.0f, 1.0f + __expf(-2.0f * x)) - 1.0f;
}

// ---------------------------------------------------------------------------
// Kernel 1: repack weights into [dir][k][u*4 + gate], gate order (i,f,g,o)
// so one LDG.128 per (k,u) yields the two natural f32x2 pairs (wi,wf),(wg,wo).
// ---------------------------------------------------------------------------
__global__ void pack_kernel(const float* __restrict__ Wih_f,
                            const float* __restrict__ Whh_f,
                            const float* __restrict__ Wih_b,
                            const float* __restrict__ Whh_b) {
    int idx = blockIdx.x * blockDim.x + threadIdx.x;
    if (idx >= 2 * 192 * GDIM) return;
    int d   = idx / (192 * GDIM);
    int rem = idx % (192 * GDIM);
    int k   = rem / GDIM;
    int q   = rem % GDIM;
    int u   = q >> 2;
    int g   = q & 3;
    int col = g * HID + u;
    if (k < HID) {
        const float* Whh = d ? Whh_b : Whh_f;
        g_Whp[(d * HID + k) * GDIM + q] = Whh[k * GDIM + col];
    } else {
        const float* Wih = d ? Wih_b : Wih_f;
        g_Wip[(d * EMBD + (k - HID)) * GDIM + q] = Wih[(k - HID) * GDIM + col];
    }
}

// ---------------------------------------------------------------------------
// Kernel 2: attention scores = softmax(relu(obs @ attn_W + attn_b), axis=1)
// ---------------------------------------------------------------------------
__global__ void attn_kernel(const float* __restrict__ obs,
                            const float* __restrict__ W,
                            const float* __restrict__ b) {
    int n = blockIdx.x;
    int tid = threadIdx.x;
    __shared__ float obs_s[128];
    __shared__ float red[128];

    obs_s[tid] = obs[n * 128 + tid];
    __syncthreads();

    float a = -1e30f;
    if (tid < T_STEPS) {
        a = b[tid];
#pragma unroll 8
        for (int k = 0; k < 128; k++) a = fmaf(obs_s[k], W[k * T_STEPS + tid], a);
        a = fmaxf(a, 0.0f);
    }
    red[tid] = a;
    __syncthreads();
    for (int s = 64; s > 0; s >>= 1) {
        if (tid < s) red[tid] = fmaxf(red[tid], red[tid + s]);
        __syncthreads();
    }
    float m = red[0];
    __syncthreads();
    float e = 0.0f;
    if (tid < T_STEPS) e = expf(a - m);
    red[tid] = e;
    __syncthreads();
    for (int s = 64; s > 0; s >>= 1) {
        if (tid < s) red[tid] += red[tid + s];
        __syncthreads();
    }
    float ssum = red[0];
    if (tid < T_STEPS) g_scores[n * T_STEPS + tid] = e / ssum;
}

// ---------------------------------------------------------------------------
// Kernel 3: precompute x-gates for ALL (dir,t,m):
//   xg = relu(feat4 @ embW + embB) @ Wih + b   (bias folded)
// Gate-pair f32x2: thread u owns unit u; accA=(i,f), accB=(g,o) per row.
// x duplicated in smem as (v,v) -> broadcast LDS.128; weights load as natural
// pairs (no MOVs). 16 rows/CTA. One barrier per t (double-buffered xs).
// ---------------------------------------------------------------------------
__global__ void __launch_bounds__(128, 5)
xgate_kernel(const float* __restrict__ lf,
             const float* __restrict__ embW, const float* __restrict__ embB,
             const float* __restrict__ b_f,  const float* __restrict__ b_b,
             int Mrows) {
    int nblk = Mrows / XROWS;
    int dir  = blockIdx.x / nblk;
    int mblk = blockIdx.x % nblk;
    int r0   = mblk * XROWS;
    int u    = threadIdx.x;

    __shared__ __align__(16) float2 xs[2][EMBD][XROWS];  // 16 KB
    __shared__ float eW[4 * EMBD];
    __shared__ float eB[EMBD];

    eW[u]       = embW[u];
    eW[u + 128] = embW[u + 128];
    if (u < EMBD) eB[u] = embB[u];

    const float* bias = dir ? b_b : b_f;
    unsigned long long bA = pack2(bias[u], bias[128 + u]);
    unsigned long long bB = pack2(bias[256 + u], bias[384 + u]);
    const float* Wbase = g_Wip + dir * EMBD * GDIM + u * 4;
    __syncthreads();

    for (int t = 0; t < T_STEPS; t++) {
        int tb = t & 1;
        // stage x_t duplicated: 16 rows x 64 e
#pragma unroll
        for (int i = 0; i < 8; i++) {
            int idx = u + i * 128;            // 0..1023 over (r,e)
            int r = idx >> 6, e = idx & 63;
            const float4 f = *(const float4*)(lf + (r0 + r) * 600 + 200 + t * 4);
            float v = eB[e];
            v = fmaf(f.x, eW[e],        v);
            v = fmaf(f.y, eW[64  + e],  v);
            v = fmaf(f.z, eW[128 + e],  v);
            v = fmaf(f.w, eW[192 + e],  v);
            v = fmaxf(v, 0.0f);
            xs[tb][e][r] = make_float2(v, v);
        }
        __syncthreads();

        unsigned long long aA[XROWS], aB[XROWS];
#pragma unroll
        for (int r = 0; r < XROWS; r++) { aA[r] = bA; aB[r] = bB; }

#pragma unroll 4
        for (int k = 0; k < EMBD; k++) {
            ulonglong2 w = *(const ulonglong2*)(Wbase + (long)k * GDIM);
#pragma unroll
            for (int pr = 0; pr < XROWS / 2; pr++) {
                ulonglong2 x2 = *(const ulonglong2*)&xs[tb][k][2 * pr];
                fma2(aA[2 * pr],     x2.x, w.x); fma2(aB[2 * pr],     x2.x, w.y);
                fma2(aA[2 * pr + 1], x2.y, w.x); fma2(aB[2 * pr + 1], x2.y, w.y);
            }
        }

        long base = ((long)(dir * T_STEPS + t) * Mrows + r0) * 128L + u;
#pragma unroll
        for (int r = 0; r < XROWS; r++) {
            ulonglong2 o; o.x = aA[r]; o.y = aB[r];
            ((ulonglong2*)g_xg)[base + (long)r * 128] = o;
        }
        // no trailing barrier: next t stages the other xs buffer
    }
}

// ---------------------------------------------------------------------------
// Kernel 4: recurrent bidirectional LSTM (h @ Whh only; x-gates preloaded).
// Gate-pair f32x2; h pre-duplicated in double-buffered smem; one barrier per
// step; next-step x-gate loads hoisted before the barrier to hide latency.
// ---------------------------------------------------------------------------
__global__ void __launch_bounds__(128, 5)
lstm_kernel(const float* __restrict__ h0, const float* __restrict__ c0,
            const int*   __restrict__ mask, int Mrows) {
    int nblk = Mrows / ROWS;
    int dir  = blockIdx.x / nblk;
    int mblk = blockIdx.x % nblk;
    int r0   = mblk * ROWS;
    int u    = threadIdx.x;

    __shared__ __align__(16) float2 hs[2][HID][ROWS];  // 16 KB

    int mrow[ROWS];
#pragma unroll
    for (int r = 0; r < ROWS; r++) mrow[r] = mask[r0 + r];

    const float* Wbase = g_Whp + dir * HID * GDIM + u * 4;
    float h0v = h0[dir * HID + u];
    float c0v = c0[dir * HID + u];

    float cst[ROWS], hmax[ROWS], hatt[ROWS];
#pragma unroll
    for (int r = 0; r < ROWS; r++) {
        cst[r] = c0v; hmax[r] = -1e30f; hatt[r] = 0.0f;
        hs[0][u][r] = make_float2(h0v, h0v);
    }

    // prologue: load x-gate accumulators for step 0
    unsigned long long aA[ROWS], aB[ROWS];
    {
        int t0 = dir ? (T_STEPS - 1) : 0;
        long base = ((long)(dir * T_STEPS + t0) * Mrows + r0) * 128L + u;
#pragma unroll
        for (int r = 0; r < ROWS; r++) {
            ulonglong2 x = ((const ulonglong2*)g_xg)[base + (long)r * 128];
            aA[r] = x.x; aB[r] = x.y;
        }
    }
    __syncthreads();

    int buf = 0;
    for (int s = 0; s < T_STEPS; s++) {
        int t = dir ? (T_STEPS - 1 - s) : s;

        // attention weights for this step (broadcast L1-hit loads)
        float av[ROWS];
#pragma unroll
        for (int r = 0; r < ROWS; r++) av[r] = __ldg(&g_scores[mrow[r] * T_STEPS + t]);

#pragma unroll 4
        for (int k = 0; k < HID; k++) {
            ulonglong2 w = *(const ulonglong2*)(Wbase + (long)k * GDIM);
            ulonglong2 h01 = *(const ulonglong2*)&hs[buf][k][0];
            ulonglong2 h23 = *(const ulonglong2*)&hs[buf][k][2];
            ulonglong2 h45 = *(const ulonglong2*)&hs[buf][k][4];
            ulonglong2 h67 = *(const ulonglong2*)&hs[buf][k][6];
            fma2(aA[0], h01.x, w.x); fma2(aB[0], h01.x, w.y);
            fma2(aA[1], h01.y, w.x); fma2(aB[1], h01.y, w.y);
            fma2(aA[2], h23.x, w.x); fma2(aB[2], h23.x, w.y);
            fma2(aA[3], h23.y, w.x); fma2(aB[3], h23.y, w.y);
            fma2(aA[4], h45.x, w.x); fma2(aB[4], h45.x, w.y);
            fma2(aA[5], h45.y, w.x); fma2(aB[5], h45.y, w.y);
            fma2(aA[6], h67.x, w.x); fma2(aB[6], h67.x, w.y);
            fma2(aA[7], h67.y, w.x); fma2(aB[7], h67.y, w.y);
        }

        // gate math + online reductions; publish h to the other buffer
#pragma unroll
        for (int r = 0; r < ROWS; r++) {
            float2 f_if = unpack2(aA[r]);   // (i, f)
            float2 f_go = unpack2(aB[r]);   // (g, o)
            float c = sigf(f_if.y) * cst[r] + sigf(f_if.x) * tanhfast(f_go.x);
            cst[r] = c;
            float h = sigf(f_go.y) * tanhfast(c);
            hmax[r] = fmaxf(hmax[r], h);
            hatt[r] = fmaf(h, av[r], hatt[r]);
            hs[buf ^ 1][u][r] = make_float2(h, h);
            if (t == 0)
                g_pre[(r0 + r) * 1024 + dir * HID + u] = h;
            if (t == T_STEPS - 1)
                g_pre[(r0 + r) * 1024 + 256 + dir * HID + u] = h;
        }

        // hoist next step's x-gate loads above the barrier (latency hiding)
        if (s + 1 < T_STEPS) {
            int tn = dir ? (T_STEPS - 2 - s) : (s + 1);
            long base = ((long)(dir * T_STEPS + tn) * Mrows + r0) * 128L + u;
#pragma unroll
            for (int r = 0; r < ROWS; r++) {
                ulonglong2 x = ((const ulonglong2*)g_xg)[base + (long)r * 128];
                aA[r] = x.x; aB[r] = x.y;
            }
        }
        __syncthreads();
        buf ^= 1;
    }

#pragma unroll
    for (int r = 0; r < ROWS; r++) {
        g_pre[(r0 + r) * 1024 + 512 + dir * HID + u] = hmax[r];
        g_pre[(r0 + r) * 1024 + 768 + dir * HID + u] = hatt[r];
    }
}

// ---------------------------------------------------------------------------
// Kernel 5: out = relu(pre(M,1024) @ enc_W(1024,128) + enc_b)
// ---------------------------------------------------------------------------
__global__ void __launch_bounds__(128)
out_kernel(const float* __restrict__ encW, const float* __restrict__ encB,
           float* __restrict__ out) {
    int r0 = blockIdx.x * ROWS;
    int c  = threadIdx.x;
    __shared__ float2 ps[ROWS / 2][64];

    float bc = encB[c];
    unsigned long long acc[ROWS / 2];
#pragma unroll
    for (int p = 0; p < ROWS / 2; p++) acc[p] = pack2(bc, bc);

    for (int kt = 0; kt < 1024; kt += 64) {
        __syncthreads();
#pragma unroll
        for (int i = 0; i < 4; i++) {
            int idx = c + i * 128;           // 0..511 over (r, kk)
            int r = idx >> 6, kk = idx & 63;
            ((float*)&ps[r >> 1][kk])[r & 1] = g_pre[(r0 + r) * 1024 + kt + kk];
        }
        __syncthreads();
#pragma unroll 4
        for (int kk = 0; kk < 64; kk++) {
            float w = encW[(kt + kk) * 128 + c];
            unsigned long long w2 = pack2(w, w);
#pragma unroll
            for (int p = 0; p < ROWS / 2; p++) {
                unsigned long long pv = *(const unsigned long long*)&ps[p][kk];
                fma2(acc[p], pv, w2);
            }
        }
    }
#pragma unroll
    for (int p = 0; p < ROWS / 2; p++) {
        float2 v = unpack2(acc[p]);
        out[(r0 + 2 * p)     * 128 + c] = fmaxf(v.x, 0.0f);
        out[(r0 + 2 * p + 1) * 128 + c] = fmaxf(v.y, 0.0f);
    }
}

// ---------------------------------------------------------------------------
// Launch
// ---------------------------------------------------------------------------
extern "C" void kernel_launch(void* const* d_in, const int* in_sizes, int n_in,
                              void* d_out, int out_size) {
    const float* lf    = (const float*)d_in[0];
    const float* obs   = (const float*)d_in[1];
    const float* embW  = (const float*)d_in[2];
    const float* embB  = (const float*)d_in[3];
    const float* attW  = (const float*)d_in[4];
    const float* attB  = (const float*)d_in[5];
    const float* Wih_f = (const float*)d_in[6];
    const float* Whh_f = (const float*)d_in[7];
    const float* b_f   = (const float*)d_in[8];
    const float* Wih_b = (const float*)d_in[9];
    const float* Whh_b = (const float*)d_in[10];
    const float* b_b   = (const float*)d_in[11];
    const float* h0    = (const float*)d_in[12];
    const float* c0    = (const float*)d_in[13];
    const float* encW  = (const float*)d_in[14];
    const float* encB  = (const float*)d_in[15];
    const int*   mask  = (const int*)d_in[16];

    int M    = in_sizes[16];       // 4096
    int Nobs = in_sizes[1] / 128;  // 256

    pack_kernel<<<(2 * 192 * GDIM + 255) / 256, 256>>>(Wih_f, Whh_f, Wih_b, Whh_b);
    attn_kernel<<<Nobs, 128>>>(obs, attW, attB);
    xgate_kernel<<<2 * (M / XROWS), 128>>>(lf, embW, embB, b_f, b_b, M);
    lstm_kernel<<<2 * (M / ROWS), 128>>>(h0, c0, mask, M);
    out_kernel<<<M / ROWS, 128>>>(encW, encB, (float*)d_out);
}